// round 14
// baseline (speedup 1.0000x reference)
#include <cuda_runtime.h>
#include <cuda_fp16.h>
#include <cstdint>
#include <cstddef>

#define NV      25000
#define NE      100000
#define NE_PAD  100096
#define NODE_IN 74
#define EDGE_IN 12
#define DOUT    64
#define EHID    128
#define NSTEPS  6

// Scratch (device globals; no runtime allocation allowed)
__device__ float  d_h[NV * DOUT];
__device__ float  d_agg[NV * DOUT];
__device__ __half d_gh[NE_PAD * EHID];
__device__ __half d_We2t[DOUT * DOUT * EHID];         // We2^T [4096][128] fp16
__device__ __half d_ew[(size_t)NE * DOUT * DOUT];     // 819 MB

// ---------------------------------------------------------------------------
// 4 nodes per block: Wp columns reused across 4 nodes.
// ---------------------------------------------------------------------------
__global__ void k_project(const float* __restrict__ nf,
                          const float* __restrict__ Wp,
                          const float* __restrict__ bp) {
    int v0 = blockIdx.x * 4;
    int o  = threadIdx.x;
    __shared__ float rows[4][NODE_IN];
    for (int i = o; i < 4 * NODE_IN; i += DOUT)
        rows[i / NODE_IN][i % NODE_IN] = nf[v0 * NODE_IN + i];
    __syncthreads();
    float b = bp[o];
    float a0 = b, a1 = b, a2 = b, a3 = b;
#pragma unroll
    for (int i = 0; i < NODE_IN; i++) {
        float w = Wp[i * DOUT + o];
        a0 += rows[0][i] * w;
        a1 += rows[1][i] * w;
        a2 += rows[2][i] * w;
        a3 += rows[3][i] * w;
    }
    d_h[(v0 + 0) * DOUT + o] = fmaxf(a0, 0.f);
    d_h[(v0 + 1) * DOUT + o] = fmaxf(a1, 0.f);
    d_h[(v0 + 2) * DOUT + o] = fmaxf(a2, 0.f);
    d_h[(v0 + 3) * DOUT + o] = fmaxf(a3, 0.f);
}

// ---------------------------------------------------------------------------
// 4 edges per 128-thread block: We1 column values reused across 4 edges.
// ---------------------------------------------------------------------------
__global__ void k_ehid(const float* __restrict__ ef,
                       const float* __restrict__ We1,
                       const float* __restrict__ be1) {
    int e0 = blockIdx.x * 4;
    int k  = threadIdx.x;
    __shared__ float rows[4][EDGE_IN];
    if (k < 4 * EDGE_IN) rows[k / EDGE_IN][k % EDGE_IN] = ef[e0 * EDGE_IN + k];
    __syncthreads();
    float b = be1[k];
    float a0 = b, a1 = b, a2 = b, a3 = b;
#pragma unroll
    for (int i = 0; i < EDGE_IN; i++) {
        float w = We1[i * EHID + k];
        a0 += rows[0][i] * w;
        a1 += rows[1][i] * w;
        a2 += rows[2][i] * w;
        a3 += rows[3][i] * w;
    }
    d_gh[(e0 + 0) * EHID + k] = __float2half(fmaxf(a0, 0.f));
    d_gh[(e0 + 1) * EHID + k] = __float2half(fmaxf(a1, 0.f));
    d_gh[(e0 + 2) * EHID + k] = __float2half(fmaxf(a2, 0.f));
    d_gh[(e0 + 3) * EHID + k] = __float2half(fmaxf(a3, 0.f));
}

// ---------------------------------------------------------------------------
__global__ void k_convW(const float* __restrict__ We2) {
    int idx = blockIdx.x * 256 + threadIdx.x;
    int n = idx >> 7, k = idx & 127;
    d_We2t[idx] = __float2half(We2[k * 4096 + n]);
}

// ---------------------------------------------------------------------------
// ew = g @ We2 + be2. HMMA m16n8k16, ldmatrix feeds, 64x64 warp tiles.
// Block tile 128 edges x 128 cols. K = 4 chunks of 32, THREE-stage cp.async
// ring. Dynamic smem 62 KB -> 3 CTAs/SM.  FROZEN (best measured: 357 us).
// ---------------------------------------------------------------------------
#define CH_STRIDE 40
#define EW_STAGE_BYTES (2 * 128 * CH_STRIDE * 2)
#define EW_SMEM_BYTES  (3 * EW_STAGE_BYTES + 512)

__device__ __forceinline__ void cp16(uint32_t smem_dst, const void* gmem_src) {
    asm volatile("cp.async.cg.shared.global [%0], [%1], 16;\n"
                 :: "r"(smem_dst), "l"(gmem_src));
}

__global__ __launch_bounds__(128, 3) void k_ew(const float* __restrict__ be2) {
    extern __shared__ __align__(16) char smem[];
    __half* sb   = (__half*)smem;
    float*  be2s = (float*)(smem + 3 * EW_STAGE_BYTES);

    int tid  = threadIdx.x;
    int warp = tid >> 5, lane = tid & 31;
    int g = lane >> 2, tig = lane & 3;
    int wm = (warp >> 1) * 64;
    int wn = (warp & 1) * 64;
    int e0 = blockIdx.y * 128;
    int n0 = blockIdx.x * 128;

    be2s[tid] = be2[n0 + tid];

    uint32_t sbase;
    asm("{ .reg .u64 t; cvta.to.shared.u64 t, %1; cvt.u32.u64 %0, t; }"
        : "=r"(sbase) : "l"(smem));

    auto load_chunk = [&](int kc, int st) {
        uint32_t stA = sbase + st * EW_STAGE_BYTES;
        uint32_t stB = stA + 128 * CH_STRIDE * 2;
#pragma unroll
        for (int it = 0; it < 4; it++) {
            int idx = tid + it * 128;
            int r = idx >> 2, j = idx & 3;
            cp16(stA + (r * CH_STRIDE + 8 * j) * 2,
                 &d_gh[(size_t)(e0 + r) * EHID + kc * 32 + 8 * j]);
            cp16(stB + (r * CH_STRIDE + 8 * j) * 2,
                 &d_We2t[(size_t)(n0 + r) * EHID + kc * 32 + 8 * j]);
        }
        asm volatile("cp.async.commit_group;\n");
    };

    load_chunk(0, 0);
    load_chunk(1, 1);
    load_chunk(2, 2);

    uint32_t offA[4], offB[4];
#pragma unroll
    for (int mt = 0; mt < 4; mt++)
        offA[mt] = (uint32_t)(((wm + mt * 16 + (lane & 15)) * CH_STRIDE +
                               (lane >> 4) * 8) * 2);
#pragma unroll
    for (int ntt = 0; ntt < 4; ntt++)
        offB[ntt] = (uint32_t)(128 * CH_STRIDE * 2 +
                               ((wn + ntt * 16 + ((lane >> 4) << 3) + (lane & 7)) *
                                CH_STRIDE + ((lane >> 3) & 1) * 8) * 2);

    float acc[4][8][4];
#pragma unroll
    for (int mt = 0; mt < 4; mt++)
#pragma unroll
        for (int nt = 0; nt < 8; nt++)
            acc[mt][nt][0] = acc[mt][nt][1] = acc[mt][nt][2] = acc[mt][nt][3] = 0.f;

#pragma unroll
    for (int kc = 0; kc < 4; kc++) {
        if (kc <= 1)      asm volatile("cp.async.wait_group 2;\n");
        else if (kc == 2) asm volatile("cp.async.wait_group 1;\n");
        else              asm volatile("cp.async.wait_group 0;\n");
        __syncthreads();

        int st = kc % 3;
        uint32_t base = sbase + st * EW_STAGE_BYTES;

#pragma unroll
        for (int kk = 0; kk < 2; kk++) {
            unsigned a[4][4];
#pragma unroll
            for (int mt = 0; mt < 4; mt++)
                asm volatile("ldmatrix.sync.aligned.m8n8.x4.shared.b16 {%0,%1,%2,%3}, [%4];"
                             : "=r"(a[mt][0]), "=r"(a[mt][1]), "=r"(a[mt][2]), "=r"(a[mt][3])
                             : "r"(base + offA[mt] + kk * 32));
#pragma unroll
            for (int ntt = 0; ntt < 4; ntt++) {
                unsigned b0, b1, b2, b3;
                asm volatile("ldmatrix.sync.aligned.m8n8.x4.shared.b16 {%0,%1,%2,%3}, [%4];"
                             : "=r"(b0), "=r"(b1), "=r"(b2), "=r"(b3)
                             : "r"(base + offB[ntt] + kk * 32));
#pragma unroll
                for (int mt = 0; mt < 4; mt++) {
                    asm volatile(
                        "mma.sync.aligned.m16n8k16.row.col.f32.f16.f16.f32 "
                        "{%0,%1,%2,%3}, {%4,%5,%6,%7}, {%8,%9}, {%0,%1,%2,%3};"
                        : "+f"(acc[mt][2*ntt][0]), "+f"(acc[mt][2*ntt][1]),
                          "+f"(acc[mt][2*ntt][2]), "+f"(acc[mt][2*ntt][3])
                        : "r"(a[mt][0]), "r"(a[mt][1]), "r"(a[mt][2]), "r"(a[mt][3]),
                          "r"(b0), "r"(b1));
                    asm volatile(
                        "mma.sync.aligned.m16n8k16.row.col.f32.f16.f16.f32 "
                        "{%0,%1,%2,%3}, {%4,%5,%6,%7}, {%8,%9}, {%0,%1,%2,%3};"
                        : "+f"(acc[mt][2*ntt+1][0]), "+f"(acc[mt][2*ntt+1][1]),
                          "+f"(acc[mt][2*ntt+1][2]), "+f"(acc[mt][2*ntt+1][3])
                        : "r"(a[mt][0]), "r"(a[mt][1]), "r"(a[mt][2]), "r"(a[mt][3]),
                          "r"(b2), "r"(b3));
                }
            }
        }
        if (kc == 0) {
            __syncthreads();
            load_chunk(3, 0);
        }
    }
    __syncthreads();

    __half(*Outs)[136] = reinterpret_cast<__half(*)[136]>(sb);
#pragma unroll
    for (int mt = 0; mt < 4; mt++)
#pragma unroll
        for (int nt = 0; nt < 8; nt++) {
            int r = wm + mt * 16 + g;
            int c = wn + nt * 8 + 2 * tig;
            __half2 v0 = __floats2half2_rn(acc[mt][nt][0] + be2s[c],
                                           acc[mt][nt][1] + be2s[c + 1]);
            __half2 v1 = __floats2half2_rn(acc[mt][nt][2] + be2s[c],
                                           acc[mt][nt][3] + be2s[c + 1]);
            *(__half2*)&Outs[r][c]     = v0;
            *(__half2*)&Outs[r + 8][c] = v1;
        }
    __syncthreads();

    for (int idx = tid; idx < 128 * 16; idx += 128) {
        int e = idx >> 4, j = idx & 15;
        if (e0 + e < NE)
            *(uint4*)&d_ew[(size_t)(e0 + e) * 4096 + n0 + 8 * j] =
                *(uint4*)&Outs[e][8 * j];
    }
}

// ---------------------------------------------------------------------------
// msg = h[src] @ ew, ReLU-sparsity compaction, TWO edges per warp with
// interleaved load streams (8 independent LDGs in flight). Per-edge
// accumulation order unchanged -> bit-identical results.
// blockDim (32,4): warp ty handles edges e0 = blk*8 + 2*ty and e0+1.
// ---------------------------------------------------------------------------
__global__ void k_msg(const int* __restrict__ src,
                      const int* __restrict__ dst) {
    int t  = threadIdx.x;
    int ty = threadIdx.y;
    int ea = blockIdx.x * 8 + ty * 2;
    int eb = ea + 1;
    __shared__ float sval[8][64];
    __shared__ int   sidx[8][64];
    int sa = ty * 2, sbq = ty * 2 + 1;

    // compaction edge A
    int s0 = src[ea];
    float a0 = d_h[s0 * 64 + t];
    float a1 = d_h[s0 * 64 + 32 + t];
    unsigned ma0 = __ballot_sync(0xffffffffu, a0 > 0.f);
    unsigned ma1 = __ballot_sync(0xffffffffu, a1 > 0.f);
    int ca = __popc(ma0);
    if (a0 > 0.f) { int p = __popc(ma0 & ((1u << t) - 1u)); sval[sa][p] = a0; sidx[sa][p] = t; }
    if (a1 > 0.f) { int p = ca + __popc(ma1 & ((1u << t) - 1u)); sval[sa][p] = a1; sidx[sa][p] = t + 32; }
    int nnza = ca + __popc(ma1);

    // compaction edge B
    int s1 = src[eb];
    float b0 = d_h[s1 * 64 + t];
    float b1 = d_h[s1 * 64 + 32 + t];
    unsigned mb0 = __ballot_sync(0xffffffffu, b0 > 0.f);
    unsigned mb1 = __ballot_sync(0xffffffffu, b1 > 0.f);
    int cb = __popc(mb0);
    if (b0 > 0.f) { int p = __popc(mb0 & ((1u << t) - 1u)); sval[sbq][p] = b0; sidx[sbq][p] = t; }
    if (b1 > 0.f) { int p = cb + __popc(mb1 & ((1u << t) - 1u)); sval[sbq][p] = b1; sidx[sbq][p] = t + 32; }
    int nnzb = cb + __popc(mb1);
    __syncwarp();

    const __half* ewa = d_ew + (size_t)ea * 4096 + 2 * t;
    const __half* ewb = d_ew + (size_t)eb * 4096 + 2 * t;
    float axa = 0.f, aya = 0.f, axb = 0.f, ayb = 0.f;
    int pa = 0, pb = 0;

    // interleaved phase: 4+4 independent loads per iteration
    while (pa + 4 <= nnza && pb + 4 <= nnzb) {
        int   ia[4], ib[4];
        float ha[4], hb[4];
        __half2 wa[4], wb[4];
#pragma unroll
        for (int u = 0; u < 4; u++) {
            ia[u] = sidx[sa][pa + u];  ha[u] = sval[sa][pa + u];
            ib[u] = sidx[sbq][pb + u]; hb[u] = sval[sbq][pb + u];
        }
#pragma unroll
        for (int u = 0; u < 4; u++) { wa[u] = *(const __half2*)(ewa + ia[u] * 64);
                                      wb[u] = *(const __half2*)(ewb + ib[u] * 64); }
#pragma unroll
        for (int u = 0; u < 4; u++) {
            float2 fa = __half22float2(wa[u]);
            float2 fb = __half22float2(wb[u]);
            axa += ha[u] * fa.x;  aya += ha[u] * fa.y;
            axb += hb[u] * fb.x;  ayb += hb[u] * fb.y;
        }
        pa += 4; pb += 4;
    }
    // drain edge A
    for (; pa + 4 <= nnza; pa += 4) {
        int ia[4]; float ha[4]; __half2 wa[4];
#pragma unroll
        for (int u = 0; u < 4; u++) { ia[u] = sidx[sa][pa + u]; ha[u] = sval[sa][pa + u]; }
#pragma unroll
        for (int u = 0; u < 4; u++) wa[u] = *(const __half2*)(ewa + ia[u] * 64);
#pragma unroll
        for (int u = 0; u < 4; u++) {
            float2 fa = __half22float2(wa[u]);
            axa += ha[u] * fa.x; aya += ha[u] * fa.y;
        }
    }
    for (; pa < nnza; pa++) {
        int i = sidx[sa][pa]; float hv = sval[sa][pa];
        float2 fa = __half22float2(*(const __half2*)(ewa + i * 64));
        axa += hv * fa.x; aya += hv * fa.y;
    }
    // drain edge B
    for (; pb + 4 <= nnzb; pb += 4) {
        int ib[4]; float hb[4]; __half2 wb[4];
#pragma unroll
        for (int u = 0; u < 4; u++) { ib[u] = sidx[sbq][pb + u]; hb[u] = sval[sbq][pb + u]; }
#pragma unroll
        for (int u = 0; u < 4; u++) wb[u] = *(const __half2*)(ewb + ib[u] * 64);
#pragma unroll
        for (int u = 0; u < 4; u++) {
            float2 fb = __half22float2(wb[u]);
            axb += hb[u] * fb.x; ayb += hb[u] * fb.y;
        }
    }
    for (; pb < nnzb; pb++) {
        int i = sidx[sbq][pb]; float hv = sval[sbq][pb];
        float2 fb = __half22float2(*(const __half2*)(ewb + i * 64));
        axb += hv * fb.x; ayb += hv * fb.y;
    }

    int da = dst[ea], db = dst[eb];
    atomicAdd(&d_agg[da * 64 + 2 * t],     axa);
    atomicAdd(&d_agg[da * 64 + 2 * t + 1], aya);
    atomicAdd(&d_agg[db * 64 + 2 * t],     axb);
    atomicAdd(&d_agg[db * 64 + 2 * t + 1], ayb);
}

// ---------------------------------------------------------------------------
__global__ void k_zero() {
    int i = blockIdx.x * blockDim.x + threadIdx.x;
    if (i < NV * DOUT) d_agg[i] = 0.f;
}

__global__ void k_relu(const float* __restrict__ bias, float* __restrict__ out) {
    int idx = blockIdx.x * blockDim.x + threadIdx.x;
    int i = idx * 4;
    if (i < NV * DOUT) {
        float4 a = *(float4*)&d_agg[i];
        float4 b = *(const float4*)&bias[i & (DOUT - 1)];
        float4 v;
        v.x = fmaxf(a.x + b.x, 0.f);
        v.y = fmaxf(a.y + b.y, 0.f);
        v.z = fmaxf(a.z + b.z, 0.f);
        v.w = fmaxf(a.w + b.w, 0.f);
        *(float4*)&d_agg[i] = make_float4(0.f, 0.f, 0.f, 0.f);
        *(float4*)&d_h[i] = v;
        if (out) *(float4*)&out[i] = v;
    }
}

// ---------------------------------------------------------------------------
extern "C" void kernel_launch(void* const* d_in, const int* in_sizes, int n_in,
                              void* d_out, int out_size) {
    const float* nf   = (const float*)d_in[0];
    const float* ef   = (const float*)d_in[1];
    const int*   src  = (const int*)  d_in[2];
    const int*   dst  = (const int*)  d_in[3];
    const float* Wp   = (const float*)d_in[4];
    const float* bp   = (const float*)d_in[5];
    const float* We1  = (const float*)d_in[6];
    const float* be1  = (const float*)d_in[7];
    const float* We2  = (const float*)d_in[8];
    const float* be2  = (const float*)d_in[9];
    const float* bias = (const float*)d_in[10];
    float* out = (float*)d_out;

    cudaFuncSetAttribute(k_ew, cudaFuncAttributeMaxDynamicSharedMemorySize,
                         EW_SMEM_BYTES);

    k_project<<<NV / 4, DOUT>>>(nf, Wp, bp);
    k_ehid<<<NE / 4, EHID>>>(ef, We1, be1);
    k_convW<<<(DOUT * DOUT * EHID) / 256, 256>>>(We2);
    k_ew<<<dim3(32, 782), 128, EW_SMEM_BYTES>>>(be2);

    k_zero<<<(NV * DOUT) / 256, 256>>>();
    for (int s = 0; s < NSTEPS; s++) {
        k_msg<<<NE / 8, dim3(32, 4)>>>(src, dst);
        k_relu<<<(NV * DOUT / 4 + 255) / 256, 256>>>(bias, (s == NSTEPS - 1) ? out : nullptr);
    }
}

// round 15
// speedup vs baseline: 1.3330x; 1.3330x over previous
#include <cuda_runtime.h>
#include <cuda_fp16.h>
#include <cstdint>
#include <cstddef>

#define NV      25000
#define NE      100000
#define NE_PAD  100096
#define NODE_IN 74
#define EDGE_IN 12
#define DOUT    64
#define EHID    128
#define NSTEPS  6

// Scratch (device globals; no runtime allocation allowed)
__device__ float  d_h[NV * DOUT];
__device__ float  d_agg[NV * DOUT];
__device__ __half d_gh[NE_PAD * EHID];
__device__ __half d_We2t[DOUT * DOUT * EHID];         // We2^T [4096][128] fp16
__device__ __half d_ew[(size_t)NE * DOUT * DOUT];     // 819 MB

// ---------------------------------------------------------------------------
// 4 nodes per block: Wp columns reused across 4 nodes.
// ---------------------------------------------------------------------------
__global__ void k_project(const float* __restrict__ nf,
                          const float* __restrict__ Wp,
                          const float* __restrict__ bp) {
    int v0 = blockIdx.x * 4;
    int o  = threadIdx.x;
    __shared__ float rows[4][NODE_IN];
    for (int i = o; i < 4 * NODE_IN; i += DOUT)
        rows[i / NODE_IN][i % NODE_IN] = nf[v0 * NODE_IN + i];
    __syncthreads();
    float b = bp[o];
    float a0 = b, a1 = b, a2 = b, a3 = b;
#pragma unroll
    for (int i = 0; i < NODE_IN; i++) {
        float w = Wp[i * DOUT + o];
        a0 += rows[0][i] * w;
        a1 += rows[1][i] * w;
        a2 += rows[2][i] * w;
        a3 += rows[3][i] * w;
    }
    d_h[(v0 + 0) * DOUT + o] = fmaxf(a0, 0.f);
    d_h[(v0 + 1) * DOUT + o] = fmaxf(a1, 0.f);
    d_h[(v0 + 2) * DOUT + o] = fmaxf(a2, 0.f);
    d_h[(v0 + 3) * DOUT + o] = fmaxf(a3, 0.f);
}

// ---------------------------------------------------------------------------
// 4 edges per 128-thread block: We1 column values reused across 4 edges.
// ---------------------------------------------------------------------------
__global__ void k_ehid(const float* __restrict__ ef,
                       const float* __restrict__ We1,
                       const float* __restrict__ be1) {
    int e0 = blockIdx.x * 4;
    int k  = threadIdx.x;
    __shared__ float rows[4][EDGE_IN];
    if (k < 4 * EDGE_IN) rows[k / EDGE_IN][k % EDGE_IN] = ef[e0 * EDGE_IN + k];
    __syncthreads();
    float b = be1[k];
    float a0 = b, a1 = b, a2 = b, a3 = b;
#pragma unroll
    for (int i = 0; i < EDGE_IN; i++) {
        float w = We1[i * EHID + k];
        a0 += rows[0][i] * w;
        a1 += rows[1][i] * w;
        a2 += rows[2][i] * w;
        a3 += rows[3][i] * w;
    }
    d_gh[(e0 + 0) * EHID + k] = __float2half(fmaxf(a0, 0.f));
    d_gh[(e0 + 1) * EHID + k] = __float2half(fmaxf(a1, 0.f));
    d_gh[(e0 + 2) * EHID + k] = __float2half(fmaxf(a2, 0.f));
    d_gh[(e0 + 3) * EHID + k] = __float2half(fmaxf(a3, 0.f));
}

// ---------------------------------------------------------------------------
__global__ void k_convW(const float* __restrict__ We2) {
    int idx = blockIdx.x * 256 + threadIdx.x;
    int n = idx >> 7, k = idx & 127;
    d_We2t[idx] = __float2half(We2[k * 4096 + n]);
}

// ---------------------------------------------------------------------------
// ew = g @ We2 + be2. HMMA m16n8k16, ldmatrix feeds, 64x64 warp tiles.
// Block tile 128 edges x 128 cols. K = 4 chunks of 32, THREE-stage cp.async
// ring. Dynamic smem 62 KB -> 3 CTAs/SM.  FROZEN (best measured: 357 us).
// ---------------------------------------------------------------------------
#define CH_STRIDE 40
#define EW_STAGE_BYTES (2 * 128 * CH_STRIDE * 2)
#define EW_SMEM_BYTES  (3 * EW_STAGE_BYTES + 512)

__device__ __forceinline__ void cp16(uint32_t smem_dst, const void* gmem_src) {
    asm volatile("cp.async.cg.shared.global [%0], [%1], 16;\n"
                 :: "r"(smem_dst), "l"(gmem_src));
}

__global__ __launch_bounds__(128, 3) void k_ew(const float* __restrict__ be2) {
    extern __shared__ __align__(16) char smem[];
    __half* sb   = (__half*)smem;
    float*  be2s = (float*)(smem + 3 * EW_STAGE_BYTES);

    int tid  = threadIdx.x;
    int warp = tid >> 5, lane = tid & 31;
    int g = lane >> 2, tig = lane & 3;
    int wm = (warp >> 1) * 64;
    int wn = (warp & 1) * 64;
    int e0 = blockIdx.y * 128;
    int n0 = blockIdx.x * 128;

    be2s[tid] = be2[n0 + tid];

    uint32_t sbase;
    asm("{ .reg .u64 t; cvta.to.shared.u64 t, %1; cvt.u32.u64 %0, t; }"
        : "=r"(sbase) : "l"(smem));

    auto load_chunk = [&](int kc, int st) {
        uint32_t stA = sbase + st * EW_STAGE_BYTES;
        uint32_t stB = stA + 128 * CH_STRIDE * 2;
#pragma unroll
        for (int it = 0; it < 4; it++) {
            int idx = tid + it * 128;
            int r = idx >> 2, j = idx & 3;
            cp16(stA + (r * CH_STRIDE + 8 * j) * 2,
                 &d_gh[(size_t)(e0 + r) * EHID + kc * 32 + 8 * j]);
            cp16(stB + (r * CH_STRIDE + 8 * j) * 2,
                 &d_We2t[(size_t)(n0 + r) * EHID + kc * 32 + 8 * j]);
        }
        asm volatile("cp.async.commit_group;\n");
    };

    load_chunk(0, 0);
    load_chunk(1, 1);
    load_chunk(2, 2);

    uint32_t offA[4], offB[4];
#pragma unroll
    for (int mt = 0; mt < 4; mt++)
        offA[mt] = (uint32_t)(((wm + mt * 16 + (lane & 15)) * CH_STRIDE +
                               (lane >> 4) * 8) * 2);
#pragma unroll
    for (int ntt = 0; ntt < 4; ntt++)
        offB[ntt] = (uint32_t)(128 * CH_STRIDE * 2 +
                               ((wn + ntt * 16 + ((lane >> 4) << 3) + (lane & 7)) *
                                CH_STRIDE + ((lane >> 3) & 1) * 8) * 2);

    float acc[4][8][4];
#pragma unroll
    for (int mt = 0; mt < 4; mt++)
#pragma unroll
        for (int nt = 0; nt < 8; nt++)
            acc[mt][nt][0] = acc[mt][nt][1] = acc[mt][nt][2] = acc[mt][nt][3] = 0.f;

#pragma unroll
    for (int kc = 0; kc < 4; kc++) {
        if (kc <= 1)      asm volatile("cp.async.wait_group 2;\n");
        else if (kc == 2) asm volatile("cp.async.wait_group 1;\n");
        else              asm volatile("cp.async.wait_group 0;\n");
        __syncthreads();

        int st = kc % 3;
        uint32_t base = sbase + st * EW_STAGE_BYTES;

#pragma unroll
        for (int kk = 0; kk < 2; kk++) {
            unsigned a[4][4];
#pragma unroll
            for (int mt = 0; mt < 4; mt++)
                asm volatile("ldmatrix.sync.aligned.m8n8.x4.shared.b16 {%0,%1,%2,%3}, [%4];"
                             : "=r"(a[mt][0]), "=r"(a[mt][1]), "=r"(a[mt][2]), "=r"(a[mt][3])
                             : "r"(base + offA[mt] + kk * 32));
#pragma unroll
            for (int ntt = 0; ntt < 4; ntt++) {
                unsigned b0, b1, b2, b3;
                asm volatile("ldmatrix.sync.aligned.m8n8.x4.shared.b16 {%0,%1,%2,%3}, [%4];"
                             : "=r"(b0), "=r"(b1), "=r"(b2), "=r"(b3)
                             : "r"(base + offB[ntt] + kk * 32));
#pragma unroll
                for (int mt = 0; mt < 4; mt++) {
                    asm volatile(
                        "mma.sync.aligned.m16n8k16.row.col.f32.f16.f16.f32 "
                        "{%0,%1,%2,%3}, {%4,%5,%6,%7}, {%8,%9}, {%0,%1,%2,%3};"
                        : "+f"(acc[mt][2*ntt][0]), "+f"(acc[mt][2*ntt][1]),
                          "+f"(acc[mt][2*ntt][2]), "+f"(acc[mt][2*ntt][3])
                        : "r"(a[mt][0]), "r"(a[mt][1]), "r"(a[mt][2]), "r"(a[mt][3]),
                          "r"(b0), "r"(b1));
                    asm volatile(
                        "mma.sync.aligned.m16n8k16.row.col.f32.f16.f16.f32 "
                        "{%0,%1,%2,%3}, {%4,%5,%6,%7}, {%8,%9}, {%0,%1,%2,%3};"
                        : "+f"(acc[mt][2*ntt+1][0]), "+f"(acc[mt][2*ntt+1][1]),
                          "+f"(acc[mt][2*ntt+1][2]), "+f"(acc[mt][2*ntt+1][3])
                        : "r"(a[mt][0]), "r"(a[mt][1]), "r"(a[mt][2]), "r"(a[mt][3]),
                          "r"(b2), "r"(b3));
                }
            }
        }
        if (kc == 0) {
            __syncthreads();
            load_chunk(3, 0);
        }
    }
    __syncthreads();

    __half(*Outs)[136] = reinterpret_cast<__half(*)[136]>(sb);
#pragma unroll
    for (int mt = 0; mt < 4; mt++)
#pragma unroll
        for (int nt = 0; nt < 8; nt++) {
            int r = wm + mt * 16 + g;
            int c = wn + nt * 8 + 2 * tig;
            __half2 v0 = __floats2half2_rn(acc[mt][nt][0] + be2s[c],
                                           acc[mt][nt][1] + be2s[c + 1]);
            __half2 v1 = __floats2half2_rn(acc[mt][nt][2] + be2s[c],
                                           acc[mt][nt][3] + be2s[c + 1]);
            *(__half2*)&Outs[r][c]     = v0;
            *(__half2*)&Outs[r + 8][c] = v1;
        }
    __syncthreads();

    for (int idx = tid; idx < 128 * 16; idx += 128) {
        int e = idx >> 4, j = idx & 15;
        if (e0 + e < NE)
            *(uint4*)&d_ew[(size_t)(e0 + e) * 4096 + n0 + 8 * j] =
                *(uint4*)&Outs[e][8 * j];
    }
}

// ---------------------------------------------------------------------------
// msg[e] = h[src[e]] @ ew[e]. R13 single-edge warp compaction (measured best),
// with __ldcs streaming loads for the read-once ew rows (keeps the reused
// d_agg/d_h set resident in L2).
// ---------------------------------------------------------------------------
__device__ __forceinline__ __half2 ldcs_h2(const __half* p) {
    unsigned v;
    asm volatile("ld.global.cs.b32 %0, [%1];" : "=r"(v) : "l"(p));
    __half2 r;
    *(unsigned*)&r = v;
    return r;
}

__global__ void k_msg(const int* __restrict__ src,
                      const int* __restrict__ dst) {
    int t  = threadIdx.x;
    int ty = threadIdx.y;
    int e  = blockIdx.x * 8 + ty;
    __shared__ float sval[8][64];
    __shared__ int   sidx[8][64];

    int s = src[e];
    float h0 = d_h[s * 64 + t];
    float h1 = d_h[s * 64 + 32 + t];
    unsigned m0 = __ballot_sync(0xffffffffu, h0 > 0.f);
    unsigned m1 = __ballot_sync(0xffffffffu, h1 > 0.f);
    int c0 = __popc(m0);
    if (h0 > 0.f) {
        int p = __popc(m0 & ((1u << t) - 1u));
        sval[ty][p] = h0; sidx[ty][p] = t;
    }
    if (h1 > 0.f) {
        int p = c0 + __popc(m1 & ((1u << t) - 1u));
        sval[ty][p] = h1; sidx[ty][p] = t + 32;
    }
    int nnz = c0 + __popc(m1);
    __syncwarp();

    const __half* ewp = d_ew + (size_t)e * 4096 + 2 * t;
    float ax = 0.f, ay = 0.f;
    int p = 0;
    for (; p + 8 <= nnz; p += 8) {
        int   iv[8];
        float hv[8];
        __half2 w[8];
#pragma unroll
        for (int u = 0; u < 8; u++) { iv[u] = sidx[ty][p + u]; hv[u] = sval[ty][p + u]; }
#pragma unroll
        for (int u = 0; u < 8; u++) w[u] = ldcs_h2(ewp + iv[u] * 64);
#pragma unroll
        for (int u = 0; u < 8; u++) {
            float2 wf = __half22float2(w[u]);
            ax += hv[u] * wf.x;
            ay += hv[u] * wf.y;
        }
    }
    for (; p + 4 <= nnz; p += 4) {
        int   iv[4];
        float hv[4];
        __half2 w[4];
#pragma unroll
        for (int u = 0; u < 4; u++) { iv[u] = sidx[ty][p + u]; hv[u] = sval[ty][p + u]; }
#pragma unroll
        for (int u = 0; u < 4; u++) w[u] = ldcs_h2(ewp + iv[u] * 64);
#pragma unroll
        for (int u = 0; u < 4; u++) {
            float2 wf = __half22float2(w[u]);
            ax += hv[u] * wf.x;
            ay += hv[u] * wf.y;
        }
    }
    for (; p < nnz; p++) {
        int   i  = sidx[ty][p];
        float hv = sval[ty][p];
        float2 wf = __half22float2(ldcs_h2(ewp + i * 64));
        ax += hv * wf.x;
        ay += hv * wf.y;
    }
    int dv = dst[e];
    atomicAdd(&d_agg[dv * 64 + 2 * t],     ax);
    atomicAdd(&d_agg[dv * 64 + 2 * t + 1], ay);
}

// ---------------------------------------------------------------------------
__global__ void k_zero() {
    int i = blockIdx.x * blockDim.x + threadIdx.x;
    if (i < NV * DOUT) d_agg[i] = 0.f;
}

__global__ void k_relu(const float* __restrict__ bias, float* __restrict__ out) {
    int idx = blockIdx.x * blockDim.x + threadIdx.x;
    int i = idx * 4;
    if (i < NV * DOUT) {
        float4 a = *(float4*)&d_agg[i];
        float4 b = *(const float4*)&bias[i & (DOUT - 1)];
        float4 v;
        v.x = fmaxf(a.x + b.x, 0.f);
        v.y = fmaxf(a.y + b.y, 0.f);
        v.z = fmaxf(a.z + b.z, 0.f);
        v.w = fmaxf(a.w + b.w, 0.f);
        *(float4*)&d_agg[i] = make_float4(0.f, 0.f, 0.f, 0.f);
        *(float4*)&d_h[i] = v;
        if (out) *(float4*)&out[i] = v;
    }
}

// ---------------------------------------------------------------------------
extern "C" void kernel_launch(void* const* d_in, const int* in_sizes, int n_in,
                              void* d_out, int out_size) {
    const float* nf   = (const float*)d_in[0];
    const float* ef   = (const float*)d_in[1];
    const int*   src  = (const int*)  d_in[2];
    const int*   dst  = (const int*)  d_in[3];
    const float* Wp   = (const float*)d_in[4];
    const float* bp   = (const float*)d_in[5];
    const float* We1  = (const float*)d_in[6];
    const float* be1  = (const float*)d_in[7];
    const float* We2  = (const float*)d_in[8];
    const float* be2  = (const float*)d_in[9];
    const float* bias = (const float*)d_in[10];
    float* out = (float*)d_out;

    cudaFuncSetAttribute(k_ew, cudaFuncAttributeMaxDynamicSharedMemorySize,
                         EW_SMEM_BYTES);

    k_project<<<NV / 4, DOUT>>>(nf, Wp, bp);
    k_ehid<<<NE / 4, EHID>>>(ef, We1, be1);
    k_convW<<<(DOUT * DOUT * EHID) / 256, 256>>>(We2);
    k_ew<<<dim3(32, 782), 128, EW_SMEM_BYTES>>>(be2);

    k_zero<<<(NV * DOUT) / 256, 256>>>();
    for (int s = 0; s < NSTEPS; s++) {
        k_msg<<<NE / 8, dim3(32, 8)>>>(src, dst);
        k_relu<<<(NV * DOUT / 4 + 255) / 256, 256>>>(bias, (s == NSTEPS - 1) ? out : nullptr);
    }
}

// round 16
// speedup vs baseline: 1.3437x; 1.0080x over previous
#include <cuda_runtime.h>
#include <cuda_fp16.h>
#include <cstdint>
#include <cstddef>

#define NV      25000
#define NE      100000
#define NE_PAD  100096
#define NODE_IN 74
#define EDGE_IN 12
#define DOUT    64
#define EHID    128
#define NSTEPS  6

// Scratch (device globals; no runtime allocation allowed)
__device__ float  d_h[NV * DOUT];
__device__ float  d_agg[NV * DOUT];
__device__ __half d_gh[NE_PAD * EHID];
__device__ __half d_We2t[DOUT * DOUT * EHID];         // We2^T [4096][128] fp16
__device__ __half d_ew[(size_t)NE * DOUT * DOUT];     // 819 MB

// ---------------------------------------------------------------------------
// Fused prologue dispatcher: one kernel, 128 threads/block, ranges by blockIdx:
//   [0, NPB)            : node projection  (8 nodes/block)
//   [NPB, NPB+NHB)      : edge-hidden MLP  (4 edges/block)
//   [.., +NWB)          : We2 transpose+convert
//   [.., +NZB)          : zero d_agg (float4)
// ---------------------------------------------------------------------------
#define NPB (NV / 8)                      // 3125
#define NHB (NE / 4)                      // 25000
#define NWB (DOUT * DOUT * EHID / 128)    // 4096
#define NZB (NV * DOUT / 4 / 128)         // 3125

__global__ __launch_bounds__(128) void k_pre(const float* __restrict__ nf,
                                             const float* __restrict__ Wp,
                                             const float* __restrict__ bp,
                                             const float* __restrict__ ef,
                                             const float* __restrict__ We1,
                                             const float* __restrict__ be1,
                                             const float* __restrict__ We2) {
    int bid = blockIdx.x;
    int tid = threadIdx.x;

    if (bid < NPB) {
        // ---- node projection: 8 nodes, two 64-thread groups of 4 nodes each
        int v0 = bid * 8;
        __shared__ float rows[8][NODE_IN];
        for (int i = tid; i < 8 * NODE_IN; i += 128)
            rows[i / NODE_IN][i % NODE_IN] = nf[v0 * NODE_IN + i];
        __syncthreads();
        int o = tid & 63;
        int vb = v0 + (tid >> 6) * 4;          // group base node
        int rb = (tid >> 6) * 4;
        float b = bp[o];
        float a0 = b, a1 = b, a2 = b, a3 = b;
#pragma unroll
        for (int i = 0; i < NODE_IN; i++) {
            float w = Wp[i * DOUT + o];
            a0 += rows[rb + 0][i] * w;
            a1 += rows[rb + 1][i] * w;
            a2 += rows[rb + 2][i] * w;
            a3 += rows[rb + 3][i] * w;
        }
        d_h[(vb + 0) * DOUT + o] = fmaxf(a0, 0.f);
        d_h[(vb + 1) * DOUT + o] = fmaxf(a1, 0.f);
        d_h[(vb + 2) * DOUT + o] = fmaxf(a2, 0.f);
        d_h[(vb + 3) * DOUT + o] = fmaxf(a3, 0.f);
        return;
    }
    bid -= NPB;

    if (bid < NHB) {
        // ---- edge-hidden MLP: 4 edges/block
        int e0 = bid * 4;
        int k  = tid;
        __shared__ float rows[4][EDGE_IN];
        if (k < 4 * EDGE_IN) rows[k / EDGE_IN][k % EDGE_IN] = ef[e0 * EDGE_IN + k];
        __syncthreads();
        float b = be1[k];
        float a0 = b, a1 = b, a2 = b, a3 = b;
#pragma unroll
        for (int i = 0; i < EDGE_IN; i++) {
            float w = We1[i * EHID + k];
            a0 += rows[0][i] * w;
            a1 += rows[1][i] * w;
            a2 += rows[2][i] * w;
            a3 += rows[3][i] * w;
        }
        d_gh[(e0 + 0) * EHID + k] = __float2half(fmaxf(a0, 0.f));
        d_gh[(e0 + 1) * EHID + k] = __float2half(fmaxf(a1, 0.f));
        d_gh[(e0 + 2) * EHID + k] = __float2half(fmaxf(a2, 0.f));
        d_gh[(e0 + 3) * EHID + k] = __float2half(fmaxf(a3, 0.f));
        return;
    }
    bid -= NHB;

    if (bid < NWB) {
        // ---- We2 [128][4096] fp32 -> We2^T [4096][128] fp16
        int idx = bid * 128 + tid;
        int n = idx >> 7, k = idx & 127;
        d_We2t[idx] = __float2half(We2[k * 4096 + n]);
        return;
    }
    bid -= NWB;

    // ---- zero d_agg
    int i = (bid * 128 + tid) * 4;
    *(float4*)&d_agg[i] = make_float4(0.f, 0.f, 0.f, 0.f);
}

// ---------------------------------------------------------------------------
// ew = g @ We2 + be2. HMMA m16n8k16, ldmatrix feeds, 64x64 warp tiles.
// Block tile 128 edges x 128 cols. K = 4 chunks of 32, THREE-stage cp.async
// ring. Dynamic smem 62 KB -> 3 CTAs/SM.  FROZEN (357 us) + __stcs stores.
// ---------------------------------------------------------------------------
#define CH_STRIDE 40
#define EW_STAGE_BYTES (2 * 128 * CH_STRIDE * 2)
#define EW_SMEM_BYTES  (3 * EW_STAGE_BYTES + 512)

__device__ __forceinline__ void cp16(uint32_t smem_dst, const void* gmem_src) {
    asm volatile("cp.async.cg.shared.global [%0], [%1], 16;\n"
                 :: "r"(smem_dst), "l"(gmem_src));
}

__global__ __launch_bounds__(128, 3) void k_ew(const float* __restrict__ be2) {
    extern __shared__ __align__(16) char smem[];
    __half* sb   = (__half*)smem;
    float*  be2s = (float*)(smem + 3 * EW_STAGE_BYTES);

    int tid  = threadIdx.x;
    int warp = tid >> 5, lane = tid & 31;
    int g = lane >> 2, tig = lane & 3;
    int wm = (warp >> 1) * 64;
    int wn = (warp & 1) * 64;
    int e0 = blockIdx.y * 128;
    int n0 = blockIdx.x * 128;

    be2s[tid] = be2[n0 + tid];

    uint32_t sbase;
    asm("{ .reg .u64 t; cvta.to.shared.u64 t, %1; cvt.u32.u64 %0, t; }"
        : "=r"(sbase) : "l"(smem));

    auto load_chunk = [&](int kc, int st) {
        uint32_t stA = sbase + st * EW_STAGE_BYTES;
        uint32_t stB = stA + 128 * CH_STRIDE * 2;
#pragma unroll
        for (int it = 0; it < 4; it++) {
            int idx = tid + it * 128;
            int r = idx >> 2, j = idx & 3;
            cp16(stA + (r * CH_STRIDE + 8 * j) * 2,
                 &d_gh[(size_t)(e0 + r) * EHID + kc * 32 + 8 * j]);
            cp16(stB + (r * CH_STRIDE + 8 * j) * 2,
                 &d_We2t[(size_t)(n0 + r) * EHID + kc * 32 + 8 * j]);
        }
        asm volatile("cp.async.commit_group;\n");
    };

    load_chunk(0, 0);
    load_chunk(1, 1);
    load_chunk(2, 2);

    uint32_t offA[4], offB[4];
#pragma unroll
    for (int mt = 0; mt < 4; mt++)
        offA[mt] = (uint32_t)(((wm + mt * 16 + (lane & 15)) * CH_STRIDE +
                               (lane >> 4) * 8) * 2);
#pragma unroll
    for (int ntt = 0; ntt < 4; ntt++)
        offB[ntt] = (uint32_t)(128 * CH_STRIDE * 2 +
                               ((wn + ntt * 16 + ((lane >> 4) << 3) + (lane & 7)) *
                                CH_STRIDE + ((lane >> 3) & 1) * 8) * 2);

    float acc[4][8][4];
#pragma unroll
    for (int mt = 0; mt < 4; mt++)
#pragma unroll
        for (int nt = 0; nt < 8; nt++)
            acc[mt][nt][0] = acc[mt][nt][1] = acc[mt][nt][2] = acc[mt][nt][3] = 0.f;

#pragma unroll
    for (int kc = 0; kc < 4; kc++) {
        if (kc <= 1)      asm volatile("cp.async.wait_group 2;\n");
        else if (kc == 2) asm volatile("cp.async.wait_group 1;\n");
        else              asm volatile("cp.async.wait_group 0;\n");
        __syncthreads();

        int st = kc % 3;
        uint32_t base = sbase + st * EW_STAGE_BYTES;

#pragma unroll
        for (int kk = 0; kk < 2; kk++) {
            unsigned a[4][4];
#pragma unroll
            for (int mt = 0; mt < 4; mt++)
                asm volatile("ldmatrix.sync.aligned.m8n8.x4.shared.b16 {%0,%1,%2,%3}, [%4];"
                             : "=r"(a[mt][0]), "=r"(a[mt][1]), "=r"(a[mt][2]), "=r"(a[mt][3])
                             : "r"(base + offA[mt] + kk * 32));
#pragma unroll
            for (int ntt = 0; ntt < 4; ntt++) {
                unsigned b0, b1, b2, b3;
                asm volatile("ldmatrix.sync.aligned.m8n8.x4.shared.b16 {%0,%1,%2,%3}, [%4];"
                             : "=r"(b0), "=r"(b1), "=r"(b2), "=r"(b3)
                             : "r"(base + offB[ntt] + kk * 32));
#pragma unroll
                for (int mt = 0; mt < 4; mt++) {
                    asm volatile(
                        "mma.sync.aligned.m16n8k16.row.col.f32.f16.f16.f32 "
                        "{%0,%1,%2,%3}, {%4,%5,%6,%7}, {%8,%9}, {%0,%1,%2,%3};"
                        : "+f"(acc[mt][2*ntt][0]), "+f"(acc[mt][2*ntt][1]),
                          "+f"(acc[mt][2*ntt][2]), "+f"(acc[mt][2*ntt][3])
                        : "r"(a[mt][0]), "r"(a[mt][1]), "r"(a[mt][2]), "r"(a[mt][3]),
                          "r"(b0), "r"(b1));
                    asm volatile(
                        "mma.sync.aligned.m16n8k16.row.col.f32.f16.f16.f32 "
                        "{%0,%1,%2,%3}, {%4,%5,%6,%7}, {%8,%9}, {%0,%1,%2,%3};"
                        : "+f"(acc[mt][2*ntt+1][0]), "+f"(acc[mt][2*ntt+1][1]),
                          "+f"(acc[mt][2*ntt+1][2]), "+f"(acc[mt][2*ntt+1][3])
                        : "r"(a[mt][0]), "r"(a[mt][1]), "r"(a[mt][2]), "r"(a[mt][3]),
                          "r"(b2), "r"(b3));
                }
            }
        }
        if (kc == 0) {
            __syncthreads();
            load_chunk(3, 0);
        }
    }
    __syncthreads();

    __half(*Outs)[136] = reinterpret_cast<__half(*)[136]>(sb);
#pragma unroll
    for (int mt = 0; mt < 4; mt++)
#pragma unroll
        for (int nt = 0; nt < 8; nt++) {
            int r = wm + mt * 16 + g;
            int c = wn + nt * 8 + 2 * tig;
            __half2 v0 = __floats2half2_rn(acc[mt][nt][0] + be2s[c],
                                           acc[mt][nt][1] + be2s[c + 1]);
            __half2 v1 = __floats2half2_rn(acc[mt][nt][2] + be2s[c],
                                           acc[mt][nt][3] + be2s[c + 1]);
            *(__half2*)&Outs[r][c]     = v0;
            *(__half2*)&Outs[r + 8][c] = v1;
        }
    __syncthreads();

    // evict-first streaming stores: ew is written once, read NSTEPS times later
    for (int idx = tid; idx < 128 * 16; idx += 128) {
        int e = idx >> 4, j = idx & 15;
        if (e0 + e < NE) {
            uint4 v = *(uint4*)&Outs[e][8 * j];
            __stcs((uint4*)&d_ew[(size_t)(e0 + e) * 4096 + n0 + 8 * j], v);
        }
    }
}

// ---------------------------------------------------------------------------
// msg[e] = h[src[e]] @ ew[e]. Single-edge warp compaction + __ldcs streaming
// ew reads (best measured).
// ---------------------------------------------------------------------------
__device__ __forceinline__ __half2 ldcs_h2(const __half* p) {
    unsigned v;
    asm volatile("ld.global.cs.b32 %0, [%1];" : "=r"(v) : "l"(p));
    __half2 r;
    *(unsigned*)&r = v;
    return r;
}

__global__ void k_msg(const int* __restrict__ src,
                      const int* __restrict__ dst) {
    int t  = threadIdx.x;
    int ty = threadIdx.y;
    int e  = blockIdx.x * 8 + ty;
    __shared__ float sval[8][64];
    __shared__ int   sidx[8][64];

    int s = src[e];
    float h0 = d_h[s * 64 + t];
    float h1 = d_h[s * 64 + 32 + t];
    unsigned m0 = __ballot_sync(0xffffffffu, h0 > 0.f);
    unsigned m1 = __ballot_sync(0xffffffffu, h1 > 0.f);
    int c0 = __popc(m0);
    if (h0 > 0.f) {
        int p = __popc(m0 & ((1u << t) - 1u));
        sval[ty][p] = h0; sidx[ty][p] = t;
    }
    if (h1 > 0.f) {
        int p = c0 + __popc(m1 & ((1u << t) - 1u));
        sval[ty][p] = h1; sidx[ty][p] = t + 32;
    }
    int nnz = c0 + __popc(m1);
    __syncwarp();

    const __half* ewp = d_ew + (size_t)e * 4096 + 2 * t;
    float ax = 0.f, ay = 0.f;
    int p = 0;
    for (; p + 8 <= nnz; p += 8) {
        int   iv[8];
        float hv[8];
        __half2 w[8];
#pragma unroll
        for (int u = 0; u < 8; u++) { iv[u] = sidx[ty][p + u]; hv[u] = sval[ty][p + u]; }
#pragma unroll
        for (int u = 0; u < 8; u++) w[u] = ldcs_h2(ewp + iv[u] * 64);
#pragma unroll
        for (int u = 0; u < 8; u++) {
            float2 wf = __half22float2(w[u]);
            ax += hv[u] * wf.x;
            ay += hv[u] * wf.y;
        }
    }
    for (; p + 4 <= nnz; p += 4) {
        int   iv[4];
        float hv[4];
        __half2 w[4];
#pragma unroll
        for (int u = 0; u < 4; u++) { iv[u] = sidx[ty][p + u]; hv[u] = sval[ty][p + u]; }
#pragma unroll
        for (int u = 0; u < 4; u++) w[u] = ldcs_h2(ewp + iv[u] * 64);
#pragma unroll
        for (int u = 0; u < 4; u++) {
            float2 wf = __half22float2(w[u]);
            ax += hv[u] * wf.x;
            ay += hv[u] * wf.y;
        }
    }
    for (; p < nnz; p++) {
        int   i  = sidx[ty][p];
        float hv = sval[ty][p];
        float2 wf = __half22float2(ldcs_h2(ewp + i * 64));
        ax += hv * wf.x;
        ay += hv * wf.y;
    }
    int dv = dst[e];
    atomicAdd(&d_agg[dv * 64 + 2 * t],     ax);
    atomicAdd(&d_agg[dv * 64 + 2 * t + 1], ay);
}

// ---------------------------------------------------------------------------
__global__ void k_relu(const float* __restrict__ bias, float* __restrict__ out) {
    int idx = blockIdx.x * blockDim.x + threadIdx.x;
    int i = idx * 4;
    if (i < NV * DOUT) {
        float4 a = *(float4*)&d_agg[i];
        float4 b = *(const float4*)&bias[i & (DOUT - 1)];
        float4 v;
        v.x = fmaxf(a.x + b.x, 0.f);
        v.y = fmaxf(a.y + b.y, 0.f);
        v.z = fmaxf(a.z + b.z, 0.f);
        v.w = fmaxf(a.w + b.w, 0.f);
        *(float4*)&d_agg[i] = make_float4(0.f, 0.f, 0.f, 0.f);
        *(float4*)&d_h[i] = v;
        if (out) *(float4*)&out[i] = v;
    }
}

// ---------------------------------------------------------------------------
extern "C" void kernel_launch(void* const* d_in, const int* in_sizes, int n_in,
                              void* d_out, int out_size) {
    const float* nf   = (const float*)d_in[0];
    const float* ef   = (const float*)d_in[1];
    const int*   src  = (const int*)  d_in[2];
    const int*   dst  = (const int*)  d_in[3];
    const float* Wp   = (const float*)d_in[4];
    const float* bp   = (const float*)d_in[5];
    const float* We1  = (const float*)d_in[6];
    const float* be1  = (const float*)d_in[7];
    const float* We2  = (const float*)d_in[8];
    const float* be2  = (const float*)d_in[9];
    const float* bias = (const float*)d_in[10];
    float* out = (float*)d_out;

    cudaFuncSetAttribute(k_ew, cudaFuncAttributeMaxDynamicSharedMemorySize,
                         EW_SMEM_BYTES);

    k_pre<<<NPB + NHB + NWB + NZB, 128>>>(nf, Wp, bp, ef, We1, be1, We2);
    k_ew<<<dim3(32, 782), 128, EW_SMEM_BYTES>>>(be2);

    for (int s = 0; s < NSTEPS; s++) {
        k_msg<<<NE / 8, dim3(32, 8)>>>(src, dst);
        k_relu<<<(NV * DOUT / 4 + 255) / 256, 256>>>(bias, (s == NSTEPS - 1) ? out : nullptr);
    }
}

// round 17
// speedup vs baseline: 1.4153x; 1.0533x over previous
#include <cuda_runtime.h>
#include <cuda_fp16.h>
#include <cstdint>
#include <cstddef>

#define NV      25000
#define NE      100000
#define NE_PAD  100096
#define NODE_IN 74
#define EDGE_IN 12
#define DOUT    64
#define EHID    128
#define NSTEPS  6

// Scratch (device globals; no runtime allocation allowed)
__device__ float  d_h[NV * DOUT];                     // projection output (step-0 input)
__device__ float  d_agg0[NV * DOUT];                  // ping-pong accumulators
__device__ float  d_agg1[NV * DOUT];
__device__ __half d_gh[NE_PAD * EHID];
__device__ __half d_We2t[DOUT * DOUT * EHID];         // We2^T [4096][128] fp16
__device__ __half d_ew[(size_t)NE * DOUT * DOUT];     // 819 MB

// ---------------------------------------------------------------------------
// Fused prologue dispatcher (128 thr/blk), ranges by blockIdx:
//   [0, NPB): node projection   [NPB, +NHB): edge MLP
//   [+NWB): We2 transpose       [+2*NZB): zero agg0 and agg1
// ---------------------------------------------------------------------------
#define NPB (NV / 8)                      // 3125
#define NHB (NE / 4)                      // 25000
#define NWB (DOUT * DOUT * EHID / 128)    // 4096
#define NZB (NV * DOUT / 4 / 128)         // 3125

__global__ __launch_bounds__(128) void k_pre(const float* __restrict__ nf,
                                             const float* __restrict__ Wp,
                                             const float* __restrict__ bp,
                                             const float* __restrict__ ef,
                                             const float* __restrict__ We1,
                                             const float* __restrict__ be1,
                                             const float* __restrict__ We2) {
    int bid = blockIdx.x;
    int tid = threadIdx.x;

    if (bid < NPB) {
        int v0 = bid * 8;
        __shared__ float rows[8][NODE_IN];
        for (int i = tid; i < 8 * NODE_IN; i += 128)
            rows[i / NODE_IN][i % NODE_IN] = nf[v0 * NODE_IN + i];
        __syncthreads();
        int o = tid & 63;
        int vb = v0 + (tid >> 6) * 4;
        int rb = (tid >> 6) * 4;
        float b = bp[o];
        float a0 = b, a1 = b, a2 = b, a3 = b;
#pragma unroll
        for (int i = 0; i < NODE_IN; i++) {
            float w = Wp[i * DOUT + o];
            a0 += rows[rb + 0][i] * w;
            a1 += rows[rb + 1][i] * w;
            a2 += rows[rb + 2][i] * w;
            a3 += rows[rb + 3][i] * w;
        }
        d_h[(vb + 0) * DOUT + o] = fmaxf(a0, 0.f);
        d_h[(vb + 1) * DOUT + o] = fmaxf(a1, 0.f);
        d_h[(vb + 2) * DOUT + o] = fmaxf(a2, 0.f);
        d_h[(vb + 3) * DOUT + o] = fmaxf(a3, 0.f);
        return;
    }
    bid -= NPB;

    if (bid < NHB) {
        int e0 = bid * 4;
        int k  = tid;
        __shared__ float rows[4][EDGE_IN];
        if (k < 4 * EDGE_IN) rows[k / EDGE_IN][k % EDGE_IN] = ef[e0 * EDGE_IN + k];
        __syncthreads();
        float b = be1[k];
        float a0 = b, a1 = b, a2 = b, a3 = b;
#pragma unroll
        for (int i = 0; i < EDGE_IN; i++) {
            float w = We1[i * EHID + k];
            a0 += rows[0][i] * w;
            a1 += rows[1][i] * w;
            a2 += rows[2][i] * w;
            a3 += rows[3][i] * w;
        }
        d_gh[(e0 + 0) * EHID + k] = __float2half(fmaxf(a0, 0.f));
        d_gh[(e0 + 1) * EHID + k] = __float2half(fmaxf(a1, 0.f));
        d_gh[(e0 + 2) * EHID + k] = __float2half(fmaxf(a2, 0.f));
        d_gh[(e0 + 3) * EHID + k] = __float2half(fmaxf(a3, 0.f));
        return;
    }
    bid -= NHB;

    if (bid < NWB) {
        int idx = bid * 128 + tid;
        int n = idx >> 7, k = idx & 127;
        d_We2t[idx] = __float2half(We2[k * 4096 + n]);
        return;
    }
    bid -= NWB;

    if (bid < NZB) {
        int i = (bid * 128 + tid) * 4;
        *(float4*)&d_agg0[i] = make_float4(0.f, 0.f, 0.f, 0.f);
        return;
    }
    bid -= NZB;
    int i = (bid * 128 + tid) * 4;
    *(float4*)&d_agg1[i] = make_float4(0.f, 0.f, 0.f, 0.f);
}

// ---------------------------------------------------------------------------
// ew = g @ We2 + be2. HMMA m16n8k16, ldmatrix, 64x64 warp tiles, 3-stage
// cp.async ring, 3 CTAs/SM, __stcs epilogue stores. FROZEN (357 us).
// ---------------------------------------------------------------------------
#define CH_STRIDE 40
#define EW_STAGE_BYTES (2 * 128 * CH_STRIDE * 2)
#define EW_SMEM_BYTES  (3 * EW_STAGE_BYTES + 512)

__device__ __forceinline__ void cp16(uint32_t smem_dst, const void* gmem_src) {
    asm volatile("cp.async.cg.shared.global [%0], [%1], 16;\n"
                 :: "r"(smem_dst), "l"(gmem_src));
}

__global__ __launch_bounds__(128, 3) void k_ew(const float* __restrict__ be2) {
    extern __shared__ __align__(16) char smem[];
    __half* sb   = (__half*)smem;
    float*  be2s = (float*)(smem + 3 * EW_STAGE_BYTES);

    int tid  = threadIdx.x;
    int warp = tid >> 5, lane = tid & 31;
    int g = lane >> 2, tig = lane & 3;
    int wm = (warp >> 1) * 64;
    int wn = (warp & 1) * 64;
    int e0 = blockIdx.y * 128;
    int n0 = blockIdx.x * 128;

    be2s[tid] = be2[n0 + tid];

    uint32_t sbase;
    asm("{ .reg .u64 t; cvta.to.shared.u64 t, %1; cvt.u32.u64 %0, t; }"
        : "=r"(sbase) : "l"(smem));

    auto load_chunk = [&](int kc, int st) {
        uint32_t stA = sbase + st * EW_STAGE_BYTES;
        uint32_t stB = stA + 128 * CH_STRIDE * 2;
#pragma unroll
        for (int it = 0; it < 4; it++) {
            int idx = tid + it * 128;
            int r = idx >> 2, j = idx & 3;
            cp16(stA + (r * CH_STRIDE + 8 * j) * 2,
                 &d_gh[(size_t)(e0 + r) * EHID + kc * 32 + 8 * j]);
            cp16(stB + (r * CH_STRIDE + 8 * j) * 2,
                 &d_We2t[(size_t)(n0 + r) * EHID + kc * 32 + 8 * j]);
        }
        asm volatile("cp.async.commit_group;\n");
    };

    load_chunk(0, 0);
    load_chunk(1, 1);
    load_chunk(2, 2);

    uint32_t offA[4], offB[4];
#pragma unroll
    for (int mt = 0; mt < 4; mt++)
        offA[mt] = (uint32_t)(((wm + mt * 16 + (lane & 15)) * CH_STRIDE +
                               (lane >> 4) * 8) * 2);
#pragma unroll
    for (int ntt = 0; ntt < 4; ntt++)
        offB[ntt] = (uint32_t)(128 * CH_STRIDE * 2 +
                               ((wn + ntt * 16 + ((lane >> 4) << 3) + (lane & 7)) *
                                CH_STRIDE + ((lane >> 3) & 1) * 8) * 2);

    float acc[4][8][4];
#pragma unroll
    for (int mt = 0; mt < 4; mt++)
#pragma unroll
        for (int nt = 0; nt < 8; nt++)
            acc[mt][nt][0] = acc[mt][nt][1] = acc[mt][nt][2] = acc[mt][nt][3] = 0.f;

#pragma unroll
    for (int kc = 0; kc < 4; kc++) {
        if (kc <= 1)      asm volatile("cp.async.wait_group 2;\n");
        else if (kc == 2) asm volatile("cp.async.wait_group 1;\n");
        else              asm volatile("cp.async.wait_group 0;\n");
        __syncthreads();

        int st = kc % 3;
        uint32_t base = sbase + st * EW_STAGE_BYTES;

#pragma unroll
        for (int kk = 0; kk < 2; kk++) {
            unsigned a[4][4];
#pragma unroll
            for (int mt = 0; mt < 4; mt++)
                asm volatile("ldmatrix.sync.aligned.m8n8.x4.shared.b16 {%0,%1,%2,%3}, [%4];"
                             : "=r"(a[mt][0]), "=r"(a[mt][1]), "=r"(a[mt][2]), "=r"(a[mt][3])
                             : "r"(base + offA[mt] + kk * 32));
#pragma unroll
            for (int ntt = 0; ntt < 4; ntt++) {
                unsigned b0, b1, b2, b3;
                asm volatile("ldmatrix.sync.aligned.m8n8.x4.shared.b16 {%0,%1,%2,%3}, [%4];"
                             : "=r"(b0), "=r"(b1), "=r"(b2), "=r"(b3)
                             : "r"(base + offB[ntt] + kk * 32));
#pragma unroll
                for (int mt = 0; mt < 4; mt++) {
                    asm volatile(
                        "mma.sync.aligned.m16n8k16.row.col.f32.f16.f16.f32 "
                        "{%0,%1,%2,%3}, {%4,%5,%6,%7}, {%8,%9}, {%0,%1,%2,%3};"
                        : "+f"(acc[mt][2*ntt][0]), "+f"(acc[mt][2*ntt][1]),
                          "+f"(acc[mt][2*ntt][2]), "+f"(acc[mt][2*ntt][3])
                        : "r"(a[mt][0]), "r"(a[mt][1]), "r"(a[mt][2]), "r"(a[mt][3]),
                          "r"(b0), "r"(b1));
                    asm volatile(
                        "mma.sync.aligned.m16n8k16.row.col.f32.f16.f16.f32 "
                        "{%0,%1,%2,%3}, {%4,%5,%6,%7}, {%8,%9}, {%0,%1,%2,%3};"
                        : "+f"(acc[mt][2*ntt+1][0]), "+f"(acc[mt][2*ntt+1][1]),
                          "+f"(acc[mt][2*ntt+1][2]), "+f"(acc[mt][2*ntt+1][3])
                        : "r"(a[mt][0]), "r"(a[mt][1]), "r"(a[mt][2]), "r"(a[mt][3]),
                          "r"(b2), "r"(b3));
                }
            }
        }
        if (kc == 0) {
            __syncthreads();
            load_chunk(3, 0);
        }
    }
    __syncthreads();

    __half(*Outs)[136] = reinterpret_cast<__half(*)[136]>(sb);
#pragma unroll
    for (int mt = 0; mt < 4; mt++)
#pragma unroll
        for (int nt = 0; nt < 8; nt++) {
            int r = wm + mt * 16 + g;
            int c = wn + nt * 8 + 2 * tig;
            __half2 v0 = __floats2half2_rn(acc[mt][nt][0] + be2s[c],
                                           acc[mt][nt][1] + be2s[c + 1]);
            __half2 v1 = __floats2half2_rn(acc[mt][nt][2] + be2s[c],
                                           acc[mt][nt][3] + be2s[c + 1]);
            *(__half2*)&Outs[r][c]     = v0;
            *(__half2*)&Outs[r + 8][c] = v1;
        }
    __syncthreads();

    for (int idx = tid; idx < 128 * 16; idx += 128) {
        int e = idx >> 4, j = idx & 15;
        if (e0 + e < NE) {
            uint4 v = *(uint4*)&Outs[e][8 * j];
            __stcs((uint4*)&d_ew[(size_t)(e0 + e) * 4096 + n0 + 8 * j], v);
        }
    }
}

// ---------------------------------------------------------------------------
// msg[e] = relu(hin[src[e]] (+bias)) @ ew[e] -> atomic into aggout.
// If bias != nullptr, h value = relu(hin + bias) computed inline (bit-identical
// to what the old k_relu stored). Warp compaction + __ldcs streaming reads.
// ---------------------------------------------------------------------------
__device__ __forceinline__ __half2 ldcs_h2(const __half* p) {
    unsigned v;
    asm volatile("ld.global.cs.b32 %0, [%1];" : "=r"(v) : "l"(p));
    __half2 r;
    *(unsigned*)&r = v;
    return r;
}

__global__ void k_msg(const int* __restrict__ src,
                      const int* __restrict__ dst,
                      const float* __restrict__ hin,
                      float* __restrict__ aggout,
                      const float* __restrict__ bias) {
    int t  = threadIdx.x;
    int ty = threadIdx.y;
    int e  = blockIdx.x * 8 + ty;
    __shared__ float sval[8][64];
    __shared__ int   sidx[8][64];

    int s = src[e];
    float h0 = hin[s * 64 + t];
    float h1 = hin[s * 64 + 32 + t];
    if (bias) {
        h0 = fmaxf(h0 + bias[t], 0.f);
        h1 = fmaxf(h1 + bias[t + 32], 0.f);
    }
    unsigned m0 = __ballot_sync(0xffffffffu, h0 > 0.f);
    unsigned m1 = __ballot_sync(0xffffffffu, h1 > 0.f);
    int c0 = __popc(m0);
    if (h0 > 0.f) {
        int p = __popc(m0 & ((1u << t) - 1u));
        sval[ty][p] = h0; sidx[ty][p] = t;
    }
    if (h1 > 0.f) {
        int p = c0 + __popc(m1 & ((1u << t) - 1u));
        sval[ty][p] = h1; sidx[ty][p] = t + 32;
    }
    int nnz = c0 + __popc(m1);
    __syncwarp();

    const __half* ewp = d_ew + (size_t)e * 4096 + 2 * t;
    float ax = 0.f, ay = 0.f;
    int p = 0;
    for (; p + 8 <= nnz; p += 8) {
        int   iv[8];
        float hv[8];
        __half2 w[8];
#pragma unroll
        for (int u = 0; u < 8; u++) { iv[u] = sidx[ty][p + u]; hv[u] = sval[ty][p + u]; }
#pragma unroll
        for (int u = 0; u < 8; u++) w[u] = ldcs_h2(ewp + iv[u] * 64);
#pragma unroll
        for (int u = 0; u < 8; u++) {
            float2 wf = __half22float2(w[u]);
            ax += hv[u] * wf.x;
            ay += hv[u] * wf.y;
        }
    }
    for (; p + 4 <= nnz; p += 4) {
        int   iv[4];
        float hv[4];
        __half2 w[4];
#pragma unroll
        for (int u = 0; u < 4; u++) { iv[u] = sidx[ty][p + u]; hv[u] = sval[ty][p + u]; }
#pragma unroll
        for (int u = 0; u < 4; u++) w[u] = ldcs_h2(ewp + iv[u] * 64);
#pragma unroll
        for (int u = 0; u < 4; u++) {
            float2 wf = __half22float2(w[u]);
            ax += hv[u] * wf.x;
            ay += hv[u] * wf.y;
        }
    }
    for (; p < nnz; p++) {
        int   i  = sidx[ty][p];
        float hv = sval[ty][p];
        float2 wf = __half22float2(ldcs_h2(ewp + i * 64));
        ax += hv * wf.x;
        ay += hv * wf.y;
    }
    int dv = dst[e];
    atomicAdd(&aggout[dv * 64 + 2 * t],     ax);
    atomicAdd(&aggout[dv * 64 + 2 * t + 1], ay);
}

// ---------------------------------------------------------------------------
__global__ void k_zero(float* __restrict__ buf) {
    int i = (blockIdx.x * blockDim.x + threadIdx.x) * 4;
    if (i < NV * DOUT)
        *(float4*)&buf[i] = make_float4(0.f, 0.f, 0.f, 0.f);
}

// final output: out = relu(agg + bias)
__global__ void k_out(const float* __restrict__ agg,
                      const float* __restrict__ bias,
                      float* __restrict__ out) {
    int idx = blockIdx.x * blockDim.x + threadIdx.x;
    int i = idx * 4;
    if (i < NV * DOUT) {
        float4 a = *(const float4*)&agg[i];
        float4 b = *(const float4*)&bias[i & (DOUT - 1)];
        float4 v;
        v.x = fmaxf(a.x + b.x, 0.f);
        v.y = fmaxf(a.y + b.y, 0.f);
        v.z = fmaxf(a.z + b.z, 0.f);
        v.w = fmaxf(a.w + b.w, 0.f);
        *(float4*)&out[i] = v;
    }
}

// ---------------------------------------------------------------------------
extern "C" void kernel_launch(void* const* d_in, const int* in_sizes, int n_in,
                              void* d_out, int out_size) {
    const float* nf   = (const float*)d_in[0];
    const float* ef   = (const float*)d_in[1];
    const int*   src  = (const int*)  d_in[2];
    const int*   dst  = (const int*)  d_in[3];
    const float* Wp   = (const float*)d_in[4];
    const float* bp   = (const float*)d_in[5];
    const float* We1  = (const float*)d_in[6];
    const float* be1  = (const float*)d_in[7];
    const float* We2  = (const float*)d_in[8];
    const float* be2  = (const float*)d_in[9];
    const float* bias = (const float*)d_in[10];
    float* out = (float*)d_out;

    cudaFuncSetAttribute(k_ew, cudaFuncAttributeMaxDynamicSharedMemorySize,
                         EW_SMEM_BYTES);

    float* agg0;  cudaGetSymbolAddress((void**)&agg0, d_agg0);
    float* agg1;  cudaGetSymbolAddress((void**)&agg1, d_agg1);
    float* hptr;  cudaGetSymbolAddress((void**)&hptr, d_h);

    k_pre<<<NPB + NHB + NWB + 2 * NZB, 128>>>(nf, Wp, bp, ef, We1, be1, We2);
    k_ew<<<dim3(32, 782), 128, EW_SMEM_BYTES>>>(be2);

    dim3 mb(32, 8);
    int ZG = (NV * DOUT / 4 + 255) / 256;

    // step 0: raw h -> agg0
    k_msg<<<NE / 8, mb>>>(src, dst, hptr, agg0, nullptr);
    // step 1: relu(agg0+bias) -> agg1
    k_msg<<<NE / 8, mb>>>(src, dst, agg0, agg1, bias);
    // steps 2..5: ping-pong, zeroing the target buffer first
    float* bufs[2] = {agg0, agg1};
    for (int s = 2; s < NSTEPS; s++) {
        float* rd = bufs[(s + 1) & 1];     // holds step s-1 result
        float* wr = bufs[s & 1];           // to be reused
        k_zero<<<ZG, 256>>>(wr);
        k_msg<<<NE / 8, mb>>>(src, dst, rd, wr, bias);
    }
    // output: relu(agg[last] + bias)
    k_out<<<ZG, 256>>>(bufs[(NSTEPS - 1) & 1], bias, out);
}